// round 1
// baseline (speedup 1.0000x reference)
#include <cuda_runtime.h>
#include <stdint.h>

// ---------------- static scratch (no allocations allowed) ----------------
#define NNODES 16000
#define NBATCH 64
#define MAXD   512
#define MAXE   262144   // actual E = 256000

__device__ float g_xl[NNODES * MAXD];
__device__ float g_xr[NNODES * MAXD];
__device__ float g_h [NNODES * MAXD];
__device__ int   g_deg[NNODES];
__device__ int   g_cur[NNODES];
__device__ int   g_ptr[NNODES + 1];
__device__ int   g_eidx[MAXE];
__device__ float g_colsum[MAXD];
__device__ float g_colsq[MAXD];
__device__ float g_msmean[MAXD];
__device__ float g_inv[MAXD];
__device__ float g_gate[NNODES];
__device__ float g_pg[NNODES];
__device__ unsigned g_mg[NBATCH];
__device__ float g_zg[NBATCH];

// ---------------- CSR build ----------------
__global__ void csr_init(int* deg, int* cur, int n) {
    int i = blockIdx.x * blockDim.x + threadIdx.x;
    if (i < n) { deg[i] = 0; cur[i] = 0; }
}

__global__ void csr_count(const int* __restrict__ dst, int* deg, int E) {
    int e = blockIdx.x * blockDim.x + threadIdx.x;
    if (e < E) atomicAdd(&deg[dst[e]], 1);
}

// single-block exclusive scan over n (<= 16384) entries
__global__ void csr_scan(const int* __restrict__ deg, int* __restrict__ ptr, int n) {
    __shared__ int ssum[1024];
    int tid = threadIdx.x;
    int per = (n + 1023) / 1024;
    int b0 = tid * per;
    int s = 0;
    for (int i = 0; i < per; i++) { int idx = b0 + i; if (idx < n) s += deg[idx]; }
    ssum[tid] = s;
    __syncthreads();
    for (int off = 1; off < 1024; off <<= 1) {
        int v = (tid >= off) ? ssum[tid - off] : 0;
        __syncthreads();
        ssum[tid] += v;
        __syncthreads();
    }
    int run = (tid == 0) ? 0 : ssum[tid - 1];
    for (int i = 0; i < per; i++) {
        int idx = b0 + i;
        if (idx < n) { ptr[idx] = run; run += deg[idx]; }
    }
    if (tid == 1023) ptr[n] = run;
}

__global__ void csr_scatter(const int* __restrict__ dst, const int* __restrict__ ptr,
                            int* cur, int* eidx, int E) {
    int e = blockIdx.x * blockDim.x + threadIdx.x;
    if (e < E) {
        int d = dst[e];
        int pos = ptr[d] + atomicAdd(&cur[d], 1);
        eidx[pos] = e;
    }
}

// ---------------- SGEMM: C[N,M] = A[N,K] @ W[K,M], optional bias+relu ----
// BM=128 BN=64 BK=16, 256 threads, 8x4 per thread. Requires N%128==0,
// M%64==0, K%16==0 (all shapes here satisfy this).
template <int EPI>
__global__ __launch_bounds__(256) void sgemm128x64(
    const float* __restrict__ A, const float* __restrict__ W,
    float* __restrict__ C, const float* __restrict__ bias,
    int N, int K, int M)
{
    __shared__ float As[16][128];
    __shared__ float Ws[16][64];
    int tid = threadIdx.x;
    int tx = tid & 15;     // column group
    int ty = tid >> 4;     // row group
    int rowBase = blockIdx.y * 128;
    int colBase = blockIdx.x * 64;

    float acc[8][4];
#pragma unroll
    for (int i = 0; i < 8; i++)
#pragma unroll
        for (int j = 0; j < 4; j++) acc[i][j] = 0.f;

    for (int kt = 0; kt < K; kt += 16) {
#pragma unroll
        for (int it = 0; it < 2; it++) {
            int slot = tid + 256 * it;          // 0..511
            int row = slot >> 2;                // 0..127
            int kq = slot & 3;                  // group of 4 k
            float4 a = *reinterpret_cast<const float4*>(
                &A[(size_t)(rowBase + row) * K + kt + kq * 4]);
            As[kq * 4 + 0][row] = a.x;
            As[kq * 4 + 1][row] = a.y;
            As[kq * 4 + 2][row] = a.z;
            As[kq * 4 + 3][row] = a.w;
        }
        {
            int k = tid >> 4;                   // 0..15
            int cq = tid & 15;                  // 0..15
            float4 w = *reinterpret_cast<const float4*>(
                &W[(size_t)(kt + k) * M + colBase + cq * 4]);
            *reinterpret_cast<float4*>(&Ws[k][cq * 4]) = w;
        }
        __syncthreads();
#pragma unroll
        for (int k = 0; k < 16; k++) {
            float ra[8], rb[4];
            *reinterpret_cast<float4*>(&ra[0]) = *reinterpret_cast<const float4*>(&As[k][ty * 8]);
            *reinterpret_cast<float4*>(&ra[4]) = *reinterpret_cast<const float4*>(&As[k][ty * 8 + 4]);
            *reinterpret_cast<float4*>(&rb[0]) = *reinterpret_cast<const float4*>(&Ws[k][tx * 4]);
#pragma unroll
            for (int i = 0; i < 8; i++)
#pragma unroll
                for (int j = 0; j < 4; j++)
                    acc[i][j] = fmaf(ra[i], rb[j], acc[i][j]);
        }
        __syncthreads();
    }

    int col = colBase + tx * 4;
    float b0 = 0.f, b1 = 0.f, b2 = 0.f, b3 = 0.f;
    if (EPI) { b0 = bias[col]; b1 = bias[col + 1]; b2 = bias[col + 2]; b3 = bias[col + 3]; }
#pragma unroll
    for (int i = 0; i < 8; i++) {
        int row = rowBase + ty * 8 + i;
        float4 o;
        o.x = acc[i][0] + b0; o.y = acc[i][1] + b1;
        o.z = acc[i][2] + b2; o.w = acc[i][3] + b3;
        if (EPI) {
            o.x = fmaxf(o.x, 0.f); o.y = fmaxf(o.y, 0.f);
            o.z = fmaxf(o.z, 0.f); o.w = fmaxf(o.w, 0.f);
        }
        *reinterpret_cast<float4*>(&C[(size_t)row * M + col]) = o;
    }
}

// ---------------- GATv2 edge phase: warp-per-dst online softmax ----------
// C = channels per head, H = 4 heads. Layout [H*C] with head-major index.
template <int C>
__global__ __launch_bounds__(256) void gat_edge(
    const float* __restrict__ xl, const float* __restrict__ xr,
    const float* __restrict__ att, const float* __restrict__ bias,
    const int* __restrict__ ptr, const int* __restrict__ eidx,
    const int* __restrict__ src, float* __restrict__ out, int n)
{
    constexpr int HC = 4 * C;
    constexpr int R = HC / 32;      // values per lane
    constexpr int CPW = C / 32;     // lane-chunks per head
    int warp = (blockIdx.x * blockDim.x + threadIdx.x) >> 5;
    int lane = threadIdx.x & 31;
    if (warp >= n) return;
    int v = warp;

    float xrv[R], attv[R], acc[R];
#pragma unroll
    for (int r = 0; r < R; r++) {
        xrv[r] = xr[(size_t)v * HC + lane + 32 * r];
        attv[r] = att[lane + 32 * r];
        acc[r] = 0.f;
    }
    float m[4] = {-1e30f, -1e30f, -1e30f, -1e30f};
    float z[4] = {0.f, 0.f, 0.f, 0.f};

    int beg = ptr[v], end = ptr[v + 1];
    for (int i = beg; i <= end; i++) {            // <= end: last iter = self-loop
        int s = (i == end) ? v : src[eidx[i]];
        float xlv[R];
        float hp[4] = {0.f, 0.f, 0.f, 0.f};
#pragma unroll
        for (int r = 0; r < R; r++) {
            xlv[r] = xl[(size_t)s * HC + lane + 32 * r];
            float t = xlv[r] + xrv[r];
            t = (t > 0.f) ? t : 0.2f * t;         // leaky_relu 0.2
            hp[r / CPW] = fmaf(t, attv[r], hp[r / CPW]);
        }
#pragma unroll
        for (int off = 16; off > 0; off >>= 1) {
#pragma unroll
            for (int h = 0; h < 4; h++)
                hp[h] += __shfl_xor_sync(0xffffffffu, hp[h], off);
        }
        float p[4], sc[4];
#pragma unroll
        for (int h = 0; h < 4; h++) {
            float nm = fmaxf(m[h], hp[h]);
            sc[h] = __expf(m[h] - nm);
            p[h] = __expf(hp[h] - nm);
            z[h] = z[h] * sc[h] + p[h];
            m[h] = nm;
        }
#pragma unroll
        for (int r = 0; r < R; r++) {
            int h = r / CPW;
            acc[r] = fmaf(acc[r], sc[h], p[h] * xlv[r]);
        }
    }
#pragma unroll
    for (int r = 0; r < R; r++) {
        int h = r / CPW;
        out[(size_t)v * HC + lane + 32 * r] =
            acc[r] / (z[h] + 1e-16f) + bias[lane + 32 * r];
    }
}

// ---------------- GraphNorm ----------------
__global__ void gn_zero(float* colsum, float* colsq) {
    int c = threadIdx.x;
    colsum[c] = 0.f; colsq[c] = 0.f;
}

__global__ void gn_colstats(const float* __restrict__ x, float* sum, float* sq, int n) {
    int d = blockDim.x;
    int c = threadIdx.x;
    int r0 = blockIdx.x * 128;
    int r1 = min(r0 + 128, n);
    float s = 0.f, q = 0.f;
    for (int r = r0; r < r1; r++) {
        float v = x[(size_t)r * d + c];
        s += v; q = fmaf(v, v, q);
    }
    atomicAdd(&sum[c], s);
    atomicAdd(&sq[c], q);
}

__global__ void gn_final(const float* sum, const float* sq, const float* gm,
                         float* msmean, float* inv, int n) {
    int c = threadIdx.x;
    float mean = sum[c] / (float)n;
    float ex2 = sq[c] / (float)n;
    float ms = gm[c];
    float var = ex2 - (2.f * ms - ms * ms) * mean * mean;
    msmean[c] = ms * mean;
    inv[c] = rsqrtf(var + 1e-5f);
}

__global__ void gn_apply(float* x, const float* __restrict__ w, const float* __restrict__ b,
                         const float* __restrict__ msmean, const float* __restrict__ inv,
                         int n, int d) {
    int i = blockIdx.x * blockDim.x + threadIdx.x;
    if (i >= n * d) return;
    int c = i % d;
    float v = (x[i] - msmean[c]) * inv[c] * w[c] + b[c];
    x[i] = fmaxf(v, 0.f);
}

// ---------------- Attentional pooling ----------------
__global__ void zero_pool(unsigned* mg, float* zg, float* out) {
    int i = blockIdx.x * blockDim.x + threadIdx.x;
    if (i < NBATCH) { mg[i] = 0u; zg[i] = 0.f; }
    if (i < NBATCH * 128) out[i] = 0.f;
}

__global__ void gate_kernel(const float* __restrict__ hidden, const float* __restrict__ aW2,
                            const float* __restrict__ ab2, const int* __restrict__ batch,
                            float* gate, unsigned* mg, int n) {
    int warp = (blockIdx.x * blockDim.x + threadIdx.x) >> 5;
    int lane = threadIdx.x & 31;
    if (warp >= n) return;
    float s = 0.f;
#pragma unroll
    for (int r = 0; r < 4; r++)
        s = fmaf(hidden[(size_t)warp * 128 + lane + 32 * r], aW2[lane + 32 * r], s);
#pragma unroll
    for (int off = 16; off > 0; off >>= 1) s += __shfl_xor_sync(0xffffffffu, s, off);
    if (lane == 0) {
        float g = s + ab2[0];
        gate[warp] = g;
        unsigned enc = __float_as_uint(g);
        enc = (g >= 0.f) ? (enc | 0x80000000u) : ~enc;
        atomicMax(&mg[batch[warp]], enc);
    }
}

__global__ void pg_kernel(const float* __restrict__ gate, const int* __restrict__ batch,
                          const unsigned* __restrict__ mg, float* pg, float* zg, int n) {
    int i = blockIdx.x * blockDim.x + threadIdx.x;
    if (i >= n) return;
    unsigned u = mg[batch[i]];
    float m = (u & 0x80000000u) ? __uint_as_float(u & 0x7FFFFFFFu) : __uint_as_float(~u);
    float p = __expf(gate[i] - m);
    pg[i] = p;
    atomicAdd(&zg[batch[i]], p);
}

__global__ void pool_accum(const float* __restrict__ x, const float* __restrict__ pg,
                           const float* __restrict__ zg, const int* __restrict__ batch,
                           float* out, int n) {
    int i = blockIdx.x * blockDim.x + threadIdx.x;
    if (i >= n * 128) return;
    int node = i >> 7;
    int c = i & 127;
    int b = batch[node];
    float a = pg[node] / (zg[b] + 1e-16f);
    atomicAdd(&out[b * 128 + c], a * x[i]);
}

// ---------------- launch ----------------
extern "C" void kernel_launch(void* const* d_in, const int* in_sizes, int n_in,
                              void* d_out, int out_size) {
    if (n_in < 28) return;
    const float* x0   = (const float*)d_in[0];
    const int*   ei   = (const int*)d_in[1];
    const int*   batch= (const int*)d_in[2];
    const int E = in_sizes[1] / 2;
    const int n = in_sizes[2];

    float *xl, *xr, *h, *colsum, *colsq, *msmean, *inv, *gate, *pg, *zg;
    int *deg, *cur, *ptr, *eidx;
    unsigned* mg;
    cudaGetSymbolAddress((void**)&xl, g_xl);
    cudaGetSymbolAddress((void**)&xr, g_xr);
    cudaGetSymbolAddress((void**)&h,  g_h);
    cudaGetSymbolAddress((void**)&deg, g_deg);
    cudaGetSymbolAddress((void**)&cur, g_cur);
    cudaGetSymbolAddress((void**)&ptr, g_ptr);
    cudaGetSymbolAddress((void**)&eidx, g_eidx);
    cudaGetSymbolAddress((void**)&colsum, g_colsum);
    cudaGetSymbolAddress((void**)&colsq, g_colsq);
    cudaGetSymbolAddress((void**)&msmean, g_msmean);
    cudaGetSymbolAddress((void**)&inv, g_inv);
    cudaGetSymbolAddress((void**)&gate, g_gate);
    cudaGetSymbolAddress((void**)&pg, g_pg);
    cudaGetSymbolAddress((void**)&mg, g_mg);
    cudaGetSymbolAddress((void**)&zg, g_zg);

    // ---- CSR by dst ----
    csr_init<<<(n + 255) / 256, 256>>>(deg, cur, n);
    csr_count<<<(E + 255) / 256, 256>>>(ei + E, deg, E);
    csr_scan<<<1, 1024>>>(deg, ptr, n);
    csr_scatter<<<(E + 255) / 256, 256>>>(ei + E, ptr, cur, eidx, E);

    struct Layer { const float *Wl, *Wr, *att, *b, *gw, *gb, *gm; int K, C; };
    Layer L[3] = {
        { (const float*)d_in[3],  (const float*)d_in[4],  (const float*)d_in[5],
          (const float*)d_in[6],  (const float*)d_in[7],  (const float*)d_in[8],
          (const float*)d_in[9],  960, 128 },
        { (const float*)d_in[10], (const float*)d_in[11], (const float*)d_in[12],
          (const float*)d_in[13], (const float*)d_in[14], (const float*)d_in[15],
          (const float*)d_in[16], 512, 64 },
        { (const float*)d_in[17], (const float*)d_in[18], (const float*)d_in[19],
          (const float*)d_in[20], (const float*)d_in[21], (const float*)d_in[22],
          (const float*)d_in[23], 256, 32 },
    };

    const float* cx = x0;
    for (int li = 0; li < 3; li++) {
        int K = L[li].K, C = L[li].C, M = 4 * C;
        dim3 grid(M / 64, n / 128);
        sgemm128x64<0><<<grid, 256>>>(cx, L[li].Wl, xl, nullptr, n, K, M);
        sgemm128x64<0><<<grid, 256>>>(cx, L[li].Wr, xr, nullptr, n, K, M);
        int eblocks = (n + 7) / 8;  // 8 warps per 256-thread block
        if (C == 128)
            gat_edge<128><<<eblocks, 256>>>(xl, xr, L[li].att, L[li].b, ptr, eidx, ei, h, n);
        else if (C == 64)
            gat_edge<64><<<eblocks, 256>>>(xl, xr, L[li].att, L[li].b, ptr, eidx, ei, h, n);
        else
            gat_edge<32><<<eblocks, 256>>>(xl, xr, L[li].att, L[li].b, ptr, eidx, ei, h, n);
        gn_zero<<<1, M>>>(colsum, colsq);
        gn_colstats<<<(n + 127) / 128, M>>>(h, colsum, colsq, n);
        gn_final<<<1, M>>>(colsum, colsq, L[li].gm, msmean, inv, n);
        gn_apply<<<(n * M + 255) / 256, 256>>>(h, L[li].gw, L[li].gb, msmean, inv, n, M);
        cx = h;
    }

    // ---- attentional pooling ----
    const float* aW1 = (const float*)d_in[24];
    const float* ab1 = (const float*)d_in[25];
    const float* aW2 = (const float*)d_in[26];
    const float* ab2 = (const float*)d_in[27];

    dim3 gridp(128 / 64, n / 128);
    sgemm128x64<1><<<gridp, 256>>>(h, aW1, xr /*hidden*/, ab1, n, 128, 128);
    zero_pool<<<32, 256>>>(mg, zg, (float*)d_out);
    gate_kernel<<<(n + 7) / 8, 256>>>(xr, aW2, ab2, batch, gate, mg, n);
    pg_kernel<<<(n + 255) / 256, 256>>>(gate, batch, mg, pg, zg, n);
    pool_accum<<<(n * 128 + 255) / 256, 256>>>(h, pg, zg, batch, (float*)d_out, n);
}

// round 4
// speedup vs baseline: 1.6437x; 1.6437x over previous
#include <cuda_runtime.h>
#include <cuda_bf16.h>
#include <stdint.h>

// ---------------- static scratch (no allocations allowed) ----------------
#define NNODES 16000
#define NBATCH 64
#define MAXD   512
#define MAXK   960
#define MAXE   262144   // actual E = 256000

__device__ float g_xl[NNODES * MAXD];
__device__ float g_xr[NNODES * MAXD];
__device__ float g_h [NNODES * MAXD];
__device__ __nv_bfloat16 g_ah[NNODES * MAXK];
__device__ __nv_bfloat16 g_al[NNODES * MAXK];
__device__ __nv_bfloat16 g_bh[2][MAXD * MAXK];
__device__ __nv_bfloat16 g_bl[2][MAXD * MAXK];
__device__ int   g_deg[NNODES];
__device__ int   g_cur[NNODES];
__device__ int   g_ptr[NNODES + 1];
__device__ int   g_eidx[MAXE];
__device__ float g_colsum[MAXD];
__device__ float g_colsq[MAXD];
__device__ float g_msmean[MAXD];
__device__ float g_inv[MAXD];
__device__ float g_gate[NNODES];
__device__ float g_pg[NNODES];
__device__ unsigned g_mg[NBATCH];
__device__ float g_zg[NBATCH];

// ---------------- small PTX helpers ----------------
__device__ __forceinline__ uint32_t smem_u32(const void* p) {
    uint32_t a;
    asm("{ .reg .u64 t; cvta.to.shared.u64 t, %1; cvt.u32.u64 %0, t; }" : "=r"(a) : "l"(p));
    return a;
}
__device__ __forceinline__ void ldsm_x4(uint32_t& r0, uint32_t& r1, uint32_t& r2,
                                        uint32_t& r3, uint32_t addr) {
    asm volatile("ldmatrix.sync.aligned.m8n8.x4.shared.b16 {%0,%1,%2,%3}, [%4];"
                 : "=r"(r0), "=r"(r1), "=r"(r2), "=r"(r3) : "r"(addr));
}
__device__ __forceinline__ void mma16816(float* c, const uint32_t* a,
                                         uint32_t b0, uint32_t b1) {
    asm volatile("mma.sync.aligned.m16n8k16.row.col.f32.bf16.bf16.f32 "
                 "{%0,%1,%2,%3}, {%4,%5,%6,%7}, {%8,%9}, {%0,%1,%2,%3};"
                 : "+f"(c[0]), "+f"(c[1]), "+f"(c[2]), "+f"(c[3])
                 : "r"(a[0]), "r"(a[1]), "r"(a[2]), "r"(a[3]), "r"(b0), "r"(b1));
}
#define CP_ASYNC16(s, g) \
    asm volatile("cp.async.cg.shared.global [%0], [%1], 16;" :: "r"(s), "l"(g))
#define CP_COMMIT() asm volatile("cp.async.commit_group;" ::: "memory")

// ---------------- CSR build ----------------
__global__ void csr_init(int* deg, int* cur, int n) {
    int i = blockIdx.x * blockDim.x + threadIdx.x;
    if (i < n) { deg[i] = 0; cur[i] = 0; }
}
__global__ void csr_count(const int* __restrict__ dst, int* deg, int E) {
    int e = blockIdx.x * blockDim.x + threadIdx.x;
    if (e < E) atomicAdd(&deg[dst[e]], 1);
}
__global__ void csr_scan(const int* __restrict__ deg, int* __restrict__ ptr, int n) {
    __shared__ int ssum[1024];
    int tid = threadIdx.x;
    int per = (n + 1023) / 1024;
    int b0 = tid * per;
    int s = 0;
    for (int i = 0; i < per; i++) { int idx = b0 + i; if (idx < n) s += deg[idx]; }
    ssum[tid] = s;
    __syncthreads();
    for (int off = 1; off < 1024; off <<= 1) {
        int v = (tid >= off) ? ssum[tid - off] : 0;
        __syncthreads();
        ssum[tid] += v;
        __syncthreads();
    }
    int run = (tid == 0) ? 0 : ssum[tid - 1];
    for (int i = 0; i < per; i++) {
        int idx = b0 + i;
        if (idx < n) { ptr[idx] = run; run += deg[idx]; }
    }
    if (tid == 1023) ptr[n] = run;
}
__global__ void csr_scatter(const int* __restrict__ dst, const int* __restrict__ ptr,
                            int* cur, int* eidx, int E) {
    int e = blockIdx.x * blockDim.x + threadIdx.x;
    if (e < E) {
        int d = dst[e];
        int pos = ptr[d] + atomicAdd(&cur[d], 1);
        eidx[pos] = e;
    }
}

// ---------------- bf16 hi/lo split kernels ----------------
__global__ void xsplit(const float* __restrict__ x, __nv_bfloat16* __restrict__ ah,
                       __nv_bfloat16* __restrict__ al, int total) {
    int i = blockIdx.x * blockDim.x + threadIdx.x;
    if (i >= total) return;
    float v = x[i];
    __nv_bfloat16 h = __float2bfloat16(v);
    ah[i] = h;
    al[i] = __float2bfloat16(v - __bfloat162float(h));
}
// W[K,M] row-major -> Bt[M,K] bf16 hi/lo (row = output col m, k contiguous)
__global__ void wsplit(const float* __restrict__ W, __nv_bfloat16* __restrict__ bh,
                       __nv_bfloat16* __restrict__ bl, int K, int M) {
    int i = blockIdx.x * blockDim.x + threadIdx.x;
    if (i >= K * M) return;
    int m = i / K, k = i - m * K;
    float v = W[(size_t)k * M + m];
    __nv_bfloat16 h = __float2bfloat16(v);
    bh[i] = h;
    bl[i] = __float2bfloat16(v - __bfloat162float(h));
}

// ---------------- bf16x3 GEMM via mma.sync (HMMA) ----------------
// C[N,M] = A[N,K] @ W[K,M];  A given as hi/lo bf16 [N,K], W^T as hi/lo [M,K].
// CTA tile 128x128, BK=32, 8 warps (2x4), warp tile 64x32 (4x4 of m16n8k16).
// smem: 2 buffers x 4 tiles (Ah,Al,Bh,Bl), each 128 rows x 80B pitch (64B data).
#define TPITCH 80
#define TBYTES (128 * TPITCH)        // 10240 per tile
#define BUFBYTES (4 * TBYTES)        // 40960 per buffer
#define GEMM_SMEM (2 * BUFBYTES)     // 81920

__device__ __forceinline__ void stage_tile(const __nv_bfloat16* __restrict__ g,
                                           int rowBase, int K, int kt,
                                           uint32_t sdst, int tid) {
#pragma unroll
    for (int i = 0; i < 2; i++) {
        int slot = tid + 256 * i;            // 0..511
        int row = slot >> 2, ch = slot & 3;  // 4 x 16B chunks per 64B row
        const __nv_bfloat16* gp = g + (size_t)(rowBase + row) * K + kt * 32 + ch * 8;
        CP_ASYNC16(sdst + row * TPITCH + ch * 16, (const void*)gp);
    }
}

template <int EPI>
__global__ __launch_bounds__(256) void gemm_mma(
    const __nv_bfloat16* __restrict__ Ah, const __nv_bfloat16* __restrict__ Al,
    const __nv_bfloat16* __restrict__ Bh, const __nv_bfloat16* __restrict__ Bl,
    float* __restrict__ C, const float* __restrict__ bias, int K, int M)
{
    extern __shared__ char smem[];
    uint32_t sb = smem_u32(smem);
    int tid = threadIdx.x, wid = tid >> 5, lane = tid & 31;
    int warp_m = wid >> 2, warp_n = wid & 3;     // 2 x 4 warps
    int rowBase = blockIdx.y * 128, colBase = blockIdx.x * 128;

    float acc[4][4][4];
#pragma unroll
    for (int mt = 0; mt < 4; mt++)
#pragma unroll
        for (int nt = 0; nt < 4; nt++)
#pragma unroll
            for (int q = 0; q < 4; q++) acc[mt][nt][q] = 0.f;

    int KT = K / 32;

    // prefetch kt=0 into buffer 0
    stage_tile(Ah, rowBase, K, 0, sb + 0 * TBYTES, tid);
    stage_tile(Al, rowBase, K, 0, sb + 1 * TBYTES, tid);
    stage_tile(Bh, colBase, K, 0, sb + 2 * TBYTES, tid);
    stage_tile(Bl, colBase, K, 0, sb + 3 * TBYTES, tid);
    CP_COMMIT();

    for (int kt = 0; kt < KT; kt++) {
        int b = kt & 1;
        if (kt + 1 < KT) {
            uint32_t d = sb + ((kt + 1) & 1) * BUFBYTES;
            stage_tile(Ah, rowBase, K, kt + 1, d + 0 * TBYTES, tid);
            stage_tile(Al, rowBase, K, kt + 1, d + 1 * TBYTES, tid);
            stage_tile(Bh, colBase, K, kt + 1, d + 2 * TBYTES, tid);
            stage_tile(Bl, colBase, K, kt + 1, d + 3 * TBYTES, tid);
            CP_COMMIT();
            asm volatile("cp.async.wait_group 1;" ::: "memory");
        } else {
            asm volatile("cp.async.wait_group 0;" ::: "memory");
        }
        __syncthreads();

        uint32_t base = sb + b * BUFBYTES;
#pragma unroll
        for (int kk = 0; kk < 2; kk++) {     // two k16 steps per BK=32
            uint32_t ah[4][4], al_[4][4];
#pragma unroll
            for (int mt = 0; mt < 4; mt++) {
                uint32_t ra = base + (uint32_t)((warp_m * 64 + mt * 16 + (lane & 15)) * TPITCH
                               + kk * 32 + (lane >> 4) * 16);
                ldsm_x4(ah[mt][0], ah[mt][1], ah[mt][2], ah[mt][3], ra);
                ldsm_x4(al_[mt][0], al_[mt][1], al_[mt][2], al_[mt][3], ra + TBYTES);
            }
#pragma unroll
            for (int np = 0; np < 2; np++) { // each x4 covers two n8 tiles
                uint32_t rb = base + 2 * TBYTES
                    + (uint32_t)((warp_n * 32 + np * 16 + ((lane >> 4) & 1) * 8 + (lane & 7)) * TPITCH
                       + kk * 32 + ((lane >> 3) & 1) * 16);
                uint32_t bh0, bh1, bh2, bh3, bl0, bl1, bl2, bl3;
                ldsm_x4(bh0, bh1, bh2, bh3, rb);
                ldsm_x4(bl0, bl1, bl2, bl3, rb + TBYTES);
#pragma unroll
                for (int mt = 0; mt < 4; mt++) {
                    mma16816(acc[mt][np * 2],     ah[mt], bh0, bh1);
                    mma16816(acc[mt][np * 2],     ah[mt], bl0, bl1);
                    mma16816(acc[mt][np * 2],     al_[mt], bh0, bh1);
                    mma16816(acc[mt][np * 2 + 1], ah[mt], bh2, bh3);
                    mma16816(acc[mt][np * 2 + 1], ah[mt], bl2, bl3);
                    mma16816(acc[mt][np * 2 + 1], al_[mt], bh2, bh3);
                }
            }
        }
        __syncthreads();
    }

    // epilogue: c0,c1 -> (row lane/4, col (lane%4)*2); c2,c3 -> row+8
#pragma unroll
    for (int mt = 0; mt < 4; mt++) {
#pragma unroll
        for (int nt = 0; nt < 4; nt++) {
            int r0 = rowBase + warp_m * 64 + mt * 16 + (lane >> 2);
            int c  = colBase + warp_n * 32 + nt * 8 + (lane & 3) * 2;
            float v0 = acc[mt][nt][0], v1 = acc[mt][nt][1];
            float v2 = acc[mt][nt][2], v3 = acc[mt][nt][3];
            if (EPI) {
                float b0 = bias[c], b1 = bias[c + 1];
                v0 = fmaxf(v0 + b0, 0.f); v1 = fmaxf(v1 + b1, 0.f);
                v2 = fmaxf(v2 + b0, 0.f); v3 = fmaxf(v3 + b1, 0.f);
            }
            *reinterpret_cast<float2*>(&C[(size_t)r0 * M + c])       = make_float2(v0, v1);
            *reinterpret_cast<float2*>(&C[(size_t)(r0 + 8) * M + c]) = make_float2(v2, v3);
        }
    }
}

// ---------------- GATv2 edge phase: warp-per-dst online softmax ----------
template <int C>
__global__ __launch_bounds__(256) void gat_edge(
    const float* __restrict__ xl, const float* __restrict__ xr,
    const float* __restrict__ att, const float* __restrict__ bias,
    const int* __restrict__ ptr, const int* __restrict__ eidx,
    const int* __restrict__ src, float* __restrict__ out, int n)
{
    constexpr int HC = 4 * C;
    constexpr int R = HC / 32;
    constexpr int CPW = C / 32;
    int warp = (blockIdx.x * blockDim.x + threadIdx.x) >> 5;
    int lane = threadIdx.x & 31;
    if (warp >= n) return;
    int v = warp;

    float xrv[R], attv[R], acc[R];
#pragma unroll
    for (int r = 0; r < R; r++) {
        xrv[r] = xr[(size_t)v * HC + lane + 32 * r];
        attv[r] = att[lane + 32 * r];
        acc[r] = 0.f;
    }
    float m[4] = {-1e30f, -1e30f, -1e30f, -1e30f};
    float z[4] = {0.f, 0.f, 0.f, 0.f};

    int beg = ptr[v], end = ptr[v + 1];
    for (int i = beg; i <= end; i++) {
        int s = (i == end) ? v : src[eidx[i]];
        float xlv[R];
        float hp[4] = {0.f, 0.f, 0.f, 0.f};
#pragma unroll
        for (int r = 0; r < R; r++) {
            xlv[r] = xl[(size_t)s * HC + lane + 32 * r];
            float t = xlv[r] + xrv[r];
            t = (t > 0.f) ? t : 0.2f * t;
            hp[r / CPW] = fmaf(t, attv[r], hp[r / CPW]);
        }
#pragma unroll
        for (int off = 16; off > 0; off >>= 1) {
#pragma unroll
            for (int h = 0; h < 4; h++)
                hp[h] += __shfl_xor_sync(0xffffffffu, hp[h], off);
        }
        float p[4], sc[4];
#pragma unroll
        for (int h = 0; h < 4; h++) {
            float nm = fmaxf(m[h], hp[h]);
            sc[h] = __expf(m[h] - nm);
            p[h] = __expf(hp[h] - nm);
            z[h] = z[h] * sc[h] + p[h];
            m[h] = nm;
        }
#pragma unroll
        for (int r = 0; r < R; r++) {
            int h = r / CPW;
            acc[r] = fmaf(acc[r], sc[h], p[h] * xlv[r]);
        }
    }
#pragma unroll
    for (int r = 0; r < R; r++) {
        int h = r / CPW;
        out[(size_t)v * HC + lane + 32 * r] =
            acc[r] / (z[h] + 1e-16f) + bias[lane + 32 * r];
    }
}

// ---------------- GraphNorm ----------------
__global__ void gn_zero(float* colsum, float* colsq) {
    int c = threadIdx.x;
    colsum[c] = 0.f; colsq[c] = 0.f;
}
__global__ void gn_colstats(const float* __restrict__ x, float* sum, float* sq, int n) {
    int d = blockDim.x;
    int c = threadIdx.x;
    int r0 = blockIdx.x * 128;
    int r1 = min(r0 + 128, n);
    float s = 0.f, q = 0.f;
    for (int r = r0; r < r1; r++) {
        float v = x[(size_t)r * d + c];
        s += v; q = fmaf(v, v, q);
    }
    atomicAdd(&sum[c], s);
    atomicAdd(&sq[c], q);
}
__global__ void gn_final(const float* sum, const float* sq, const float* gm,
                         float* msmean, float* inv, int n) {
    int c = threadIdx.x;
    float mean = sum[c] / (float)n;
    float ex2 = sq[c] / (float)n;
    float ms = gm[c];
    float var = ex2 - (2.f * ms - ms * ms) * mean * mean;
    msmean[c] = ms * mean;
    inv[c] = rsqrtf(var + 1e-5f);
}
// normalize + relu, and emit bf16 hi/lo split for next GEMM
__global__ void gn_apply_fused(float* x, const float* __restrict__ w, const float* __restrict__ b,
                               const float* __restrict__ msmean, const float* __restrict__ inv,
                               __nv_bfloat16* __restrict__ ah, __nv_bfloat16* __restrict__ al,
                               int n, int d) {
    int i = blockIdx.x * blockDim.x + threadIdx.x;
    if (i >= n * d) return;
    int c = i % d;
    float v = (x[i] - msmean[c]) * inv[c] * w[c] + b[c];
    v = fmaxf(v, 0.f);
    x[i] = v;
    __nv_bfloat16 h = __float2bfloat16(v);
    ah[i] = h;
    al[i] = __float2bfloat16(v - __bfloat162float(h));
}

// ---------------- Attentional pooling ----------------
__global__ void zero_pool(unsigned* mg, float* zg, float* out) {
    int i = blockIdx.x * blockDim.x + threadIdx.x;
    if (i < NBATCH) { mg[i] = 0u; zg[i] = 0.f; }
    if (i < NBATCH * 128) out[i] = 0.f;
}
__global__ void gate_kernel(const float* __restrict__ hidden, const float* __restrict__ aW2,
                            const float* __restrict__ ab2, const int* __restrict__ batch,
                            float* gate, unsigned* mg, int n) {
    int warp = (blockIdx.x * blockDim.x + threadIdx.x) >> 5;
    int lane = threadIdx.x & 31;
    if (warp >= n) return;
    float s = 0.f;
#pragma unroll
    for (int r = 0; r < 4; r++)
        s = fmaf(hidden[(size_t)warp * 128 + lane + 32 * r], aW2[lane + 32 * r], s);
#pragma unroll
    for (int off = 16; off > 0; off >>= 1) s += __shfl_xor_sync(0xffffffffu, s, off);
    if (lane == 0) {
        float g = s + ab2[0];
        gate[warp] = g;
        unsigned enc = __float_as_uint(g);
        enc = (g >= 0.f) ? (enc | 0x80000000u) : ~enc;
        atomicMax(&mg[batch[warp]], enc);
    }
}
__global__ void pg_kernel(const float* __restrict__ gate, const int* __restrict__ batch,
                          const unsigned* __restrict__ mg, float* pg, float* zg, int n) {
    int i = blockIdx.x * blockDim.x + threadIdx.x;
    if (i >= n) return;
    unsigned u = mg[batch[i]];
    float m = (u & 0x80000000u) ? __uint_as_float(u & 0x7FFFFFFFu) : __uint_as_float(~u);
    float p = __expf(gate[i] - m);
    pg[i] = p;
    atomicAdd(&zg[batch[i]], p);
}
__global__ void pool_accum(const float* __restrict__ x, const float* __restrict__ pg,
                           const float* __restrict__ zg, const int* __restrict__ batch,
                           float* out, int n) {
    int i = blockIdx.x * blockDim.x + threadIdx.x;
    if (i >= n * 128) return;
    int node = i >> 7;
    int c = i & 127;
    int b = batch[node];
    float a = pg[node] / (zg[b] + 1e-16f);
    atomicAdd(&out[b * 128 + c], a * x[i]);
}

// ---------------- launch ----------------
extern "C" void kernel_launch(void* const* d_in, const int* in_sizes, int n_in,
                              void* d_out, int out_size) {
    if (n_in < 28) return;
    const float* x0    = (const float*)d_in[0];
    const int*   ei    = (const int*)d_in[1];
    const int*   batch = (const int*)d_in[2];
    const int E = in_sizes[1] / 2;
    const int n = in_sizes[2];

    float *xl, *xr, *h, *colsum, *colsq, *msmean, *inv, *gate, *pg, *zg;
    __nv_bfloat16 *ah, *al, *bh, *bl;
    int *deg, *cur, *ptr, *eidx;
    unsigned* mg;
    cudaGetSymbolAddress((void**)&xl, g_xl);
    cudaGetSymbolAddress((void**)&xr, g_xr);
    cudaGetSymbolAddress((void**)&h,  g_h);
    cudaGetSymbolAddress((void**)&ah, g_ah);
    cudaGetSymbolAddress((void**)&al, g_al);
    cudaGetSymbolAddress((void**)&bh, g_bh);
    cudaGetSymbolAddress((void**)&bl, g_bl);
    cudaGetSymbolAddress((void**)&deg, g_deg);
    cudaGetSymbolAddress((void**)&cur, g_cur);
    cudaGetSymbolAddress((void**)&ptr, g_ptr);
    cudaGetSymbolAddress((void**)&eidx, g_eidx);
    cudaGetSymbolAddress((void**)&colsum, g_colsum);
    cudaGetSymbolAddress((void**)&colsq, g_colsq);
    cudaGetSymbolAddress((void**)&msmean, g_msmean);
    cudaGetSymbolAddress((void**)&inv, g_inv);
    cudaGetSymbolAddress((void**)&gate, g_gate);
    cudaGetSymbolAddress((void**)&pg, g_pg);
    cudaGetSymbolAddress((void**)&mg, g_mg);
    cudaGetSymbolAddress((void**)&zg, g_zg);
    __nv_bfloat16* bh1 = bh + (size_t)MAXD * MAXK;
    __nv_bfloat16* bl1 = bl + (size_t)MAXD * MAXK;

    cudaFuncSetAttribute(gemm_mma<0>, cudaFuncAttributeMaxDynamicSharedMemorySize, GEMM_SMEM);
    cudaFuncSetAttribute(gemm_mma<1>, cudaFuncAttributeMaxDynamicSharedMemorySize, GEMM_SMEM);

    // ---- CSR by dst ----
    csr_init<<<(n + 255) / 256, 256>>>(deg, cur, n);
    csr_count<<<(E + 255) / 256, 256>>>(ei + E, deg, E);
    csr_scan<<<1, 1024>>>(deg, ptr, n);
    csr_scatter<<<(E + 255) / 256, 256>>>(ei + E, ptr, cur, eidx, E);

    struct Layer { const float *Wl, *Wr, *att, *b, *gw, *gb, *gm; int K, C; };
    Layer L[3] = {
        { (const float*)d_in[3],  (const float*)d_in[4],  (const float*)d_in[5],
          (const float*)d_in[6],  (const float*)d_in[7],  (const float*)d_in[8],
          (const float*)d_in[9],  960, 128 },
        { (const float*)d_in[10], (const float*)d_in[11], (const float*)d_in[12],
          (const float*)d_in[13], (const float*)d_in[14], (const float*)d_in[15],
          (const float*)d_in[16], 512, 64 },
        { (const float*)d_in[17], (const float*)d_in[18], (const float*)d_in[19],
          (const float*)d_in[20], (const float*)d_in[21], (const float*)d_in[22],
          (const float*)d_in[23], 256, 32 },
    };

    // split x0 -> bf16 hi/lo
    xsplit<<<(n * 960 + 255) / 256, 256>>>(x0, ah, al, n * 960);

    for (int li = 0; li < 3; li++) {
        int K = L[li].K, C = L[li].C, M = 4 * C;
        wsplit<<<(K * M + 255) / 256, 256>>>(L[li].Wl, bh, bl, K, M);
        wsplit<<<(K * M + 255) / 256, 256>>>(L[li].Wr, bh1, bl1, K, M);
        dim3 grid(M / 128, n / 128);
        gemm_mma<0><<<grid, 256, GEMM_SMEM>>>(ah, al, bh, bl, xl, nullptr, K, M);
        gemm_mma<0><<<grid, 256, GEMM_SMEM>>>(ah, al, bh1, bl1, xr, nullptr, K, M);
        int eblocks = (n + 7) / 8;
        if (C == 128)
            gat_edge<128><<<eblocks, 256>>>(xl, xr, L[li].att, L[li].b, ptr, eidx, ei, h, n);
        else if (C == 64)
            gat_edge<64><<<eblocks, 256>>>(xl, xr, L[li].att, L[li].b, ptr, eidx, ei, h, n);
        else
            gat_edge<32><<<eblocks, 256>>>(xl, xr, L[li].att, L[li].b, ptr, eidx, ei, h, n);
        gn_zero<<<1, M>>>(colsum, colsq);
        gn_colstats<<<(n + 127) / 128, M>>>(h, colsum, colsq, n);
        gn_final<<<1, M>>>(colsum, colsq, L[li].gm, msmean, inv, n);
        gn_apply_fused<<<(n * M + 255) / 256, 256>>>(h, L[li].gw, L[li].gb, msmean, inv,
                                                     ah, al, n, M);
    }

    // ---- attentional pooling ----
    const float* aW1 = (const float*)d_in[24];
    const float* ab1 = (const float*)d_in[25];
    const float* aW2 = (const float*)d_in[26];
    const float* ab2 = (const float*)d_in[27];

    wsplit<<<(128 * 128 + 255) / 256, 256>>>(aW1, bh, bl, 128, 128);
    dim3 gridp(1, n / 128);
    gemm_mma<1><<<gridp, 256, GEMM_SMEM>>>(ah, al, bh, bl, xr /*hidden*/, ab1, 128, 128);
    zero_pool<<<32, 256>>>(mg, zg, (float*)d_out);
    gate_kernel<<<(n + 7) / 8, 256>>>(xr, aW2, ab2, batch, gate, mg, n);
    pg_kernel<<<(n + 255) / 256, 256>>>(gate, batch, mg, pg, zg, n);
    pool_accum<<<(n * 128 + 255) / 256, 256>>>(h, pg, zg, batch, (float*)d_out, n);
}